// round 3
// baseline (speedup 1.0000x reference)
#include <cuda_runtime.h>
#include <math.h>

#define SPOS 576      // B*Ho*Wo = 4*12*12
#define CDIM 288      // KH*KW*Fin
#define FDIM 32
#define ODIM 16
#define IDIM 8
#define CBLK 8
#define STILE 32

// Scratch (no allocations allowed)
__device__ float g_patch[(size_t)SPOS * CDIM * IDIM];          // 5.3 MB
__device__ float g_agree[(size_t)SPOS * CDIM * FDIM];          // 21 MB, [s][c][f]
__device__ float g_cct[(size_t)FDIM * SPOS * CDIM];            // 21 MB, [f][s*C+c]

__device__ __forceinline__ float dot8(const float4 a0, const float4 a1,
                                      const float4 b0, const float4 b1) {
    return a0.x*b0.x + a0.y*b0.y + a0.z*b0.z + a0.w*b0.w
         + a1.x*b1.x + a1.y*b1.y + a1.z*b1.z + a1.w*b1.w;
}

// ---------------------------------------------------------------------------
// K0: im2col — patch[s, c, i] = x[b, h+kh, w+kw, fin, i]
// ---------------------------------------------------------------------------
__global__ void k_extract(const float4* __restrict__ x4) {
    int idx = blockIdx.x * blockDim.x + threadIdx.x;   // over SPOS*CDIM*2 float4s
    if (idx >= SPOS * CDIM * 2) return;
    int v = idx & 1;
    int c = (idx >> 1) % CDIM;
    int s = idx / (CDIM * 2);
    int w = s % 12, h = (s / 12) % 12, b = s / 144;
    int fin = c & 31, kw = (c >> 5) % 3, kh = c / 96;
    int xi = (((b * 14 + h + kh) * 14 + (w + kw)) * 32 + fin) * 2 + v;
    ((float4*)g_patch)[idx] = x4[xi];
}

// ---------------------------------------------------------------------------
// K1: per (f, s-tile of 32): centroid1 -> squash -> out1 (smem); then
//     agreement[s,c] = sum_o preds*out1, written to g_agree[s][c][f].
// Layout: 128 threads = 4 warps. Phase1: warp = 4 o's, lane = s.
//         Phase2: warp = c-sublane, lane = s.
// ---------------------------------------------------------------------------
__global__ void __launch_bounds__(128) k_phase1(const float* __restrict__ Wg) {
    const int f = blockIdx.x, st = blockIdx.y;
    const int tid = threadIdx.x, warp = tid >> 5, lane = tid & 31;
    const int s = lane;

    __shared__ float Wsm[CBLK * ODIM * IDIM];       // [c][o][i], 1024 f
    __shared__ float Psm[STILE][CBLK * IDIM + 4];   // row stride 68 (conflict-free f4)
    __shared__ float Cent[STILE][17];
    __shared__ float Out1[STILE][17];
    __shared__ float Fac[STILE];

    const float* Wf = Wg + (size_t)f * CDIM * ODIM * IDIM;
    float a0 = 0.f, a1 = 0.f, a2 = 0.f, a3 = 0.f;

    for (int c0 = 0; c0 < CDIM; c0 += CBLK) {
        __syncthreads();
        {   // W chunk is contiguous: CBLK*128 floats
            const float4* src = (const float4*)(Wf + c0 * ODIM * IDIM);
            float4* dst = (float4*)Wsm;
            dst[tid] = src[tid];
            dst[tid + 128] = src[tid + 128];
            #pragma unroll
            for (int k = tid; k < STILE * CBLK * IDIM / 4; k += 128) {
                int ss = k >> 4, q = k & 15;
                float4 pv = ((const float4*)(g_patch +
                    ((size_t)(st * STILE + ss) * CDIM + c0) * IDIM))[q];
                *(float4*)&Psm[ss][q * 4] = pv;
            }
        }
        __syncthreads();
        #pragma unroll
        for (int cc = 0; cc < CBLK; cc++) {
            float4 pa = *(const float4*)&Psm[s][cc * 8];
            float4 pb = *(const float4*)&Psm[s][cc * 8 + 4];
            const float4* wr = (const float4*)&Wsm[(cc * 16 + warp * 4) * 8];
            a0 += dot8(wr[0], wr[1], pa, pb);
            a1 += dot8(wr[2], wr[3], pa, pb);
            a2 += dot8(wr[4], wr[5], pa, pb);
            a3 += dot8(wr[6], wr[7], pa, pb);
        }
    }

    const float inv32 = 1.f / 32.f;
    Cent[s][warp * 4 + 0] = a0 * inv32;
    Cent[s][warp * 4 + 1] = a1 * inv32;
    Cent[s][warp * 4 + 2] = a2 * inv32;
    Cent[s][warp * 4 + 3] = a3 * inv32;
    __syncthreads();
    if (tid < STILE) {
        float sn = 0.f;
        #pragma unroll
        for (int o = 0; o < 16; o++) { float v = Cent[tid][o]; sn += v * v; }
        Fac[tid] = sn / ((1.f + sn) * sqrtf(sn + 1e-7f));
    }
    __syncthreads();
    {
        float fc = Fac[s] * inv32;
        Out1[s][warp * 4 + 0] = a0 * fc;
        Out1[s][warp * 4 + 1] = a1 * fc;
        Out1[s][warp * 4 + 2] = a2 * fc;
        Out1[s][warp * 4 + 3] = a3 * fc;
    }

    // ---- phase 2: agreement ----
    for (int c0 = 0; c0 < CDIM; c0 += CBLK) {
        __syncthreads();
        {
            const float4* src = (const float4*)(Wf + c0 * ODIM * IDIM);
            float4* dst = (float4*)Wsm;
            dst[tid] = src[tid];
            dst[tid + 128] = src[tid + 128];
            #pragma unroll
            for (int k = tid; k < STILE * CBLK * IDIM / 4; k += 128) {
                int ss = k >> 4, q = k & 15;
                float4 pv = ((const float4*)(g_patch +
                    ((size_t)(st * STILE + ss) * CDIM + c0) * IDIM))[q];
                *(float4*)&Psm[ss][q * 4] = pv;
            }
        }
        __syncthreads();
        #pragma unroll
        for (int half = 0; half < 2; half++) {
            int cc = half * 4 + warp;
            float4 pa = *(const float4*)&Psm[s][cc * 8];
            float4 pb = *(const float4*)&Psm[s][cc * 8 + 4];
            float agr = 0.f;
            #pragma unroll
            for (int o = 0; o < 16; o++) {
                const float4* wr = (const float4*)&Wsm[(cc * 16 + o) * 8];
                float pred = dot8(wr[0], wr[1], pa, pb);
                agr += pred * Out1[s][o];
            }
            g_agree[((size_t)(st * STILE + s) * CDIM + c0 + cc) * FDIM + f] = agr;
        }
    }
}

// ---------------------------------------------------------------------------
// K2: softmax over f per (s,c) row; logits = agreement (initial logits are 0).
// Writes f-major cc for coalesced reads in K3.
// ---------------------------------------------------------------------------
__global__ void k_softmax() {
    int row = blockIdx.x * blockDim.x + threadIdx.x;
    if (row >= SPOS * CDIM) return;
    float v[32];
    const float4* a = (const float4*)(g_agree + (size_t)row * 32);
    #pragma unroll
    for (int q = 0; q < 8; q++) {
        float4 t = a[q];
        v[q*4] = t.x; v[q*4+1] = t.y; v[q*4+2] = t.z; v[q*4+3] = t.w;
    }
    float mx = v[0];
    #pragma unroll
    for (int ff = 1; ff < 32; ff++) mx = fmaxf(mx, v[ff]);
    float sum = 0.f;
    #pragma unroll
    for (int ff = 0; ff < 32; ff++) { v[ff] = __expf(v[ff] - mx); sum += v[ff]; }
    float inv = 1.f / sum;
    #pragma unroll
    for (int ff = 0; ff < 32; ff++)
        g_cct[(size_t)ff * (SPOS * CDIM) + row] = v[ff] * inv;
}

// ---------------------------------------------------------------------------
// K3: centroid2 = sum_c cc * preds ; squash ; write output [s][f][o]
// ---------------------------------------------------------------------------
__global__ void __launch_bounds__(128) k_phase3(const float* __restrict__ Wg,
                                                float* __restrict__ out) {
    const int f = blockIdx.x, st = blockIdx.y;
    const int tid = threadIdx.x, warp = tid >> 5, lane = tid & 31;
    const int s = lane;

    __shared__ float Wsm[CBLK * ODIM * IDIM];
    __shared__ float Psm[STILE][CBLK * IDIM + 4];
    __shared__ float Csm[STILE][12];
    __shared__ float Cent[STILE][17];
    __shared__ float Fac[STILE];

    const float* Wf  = Wg + (size_t)f * CDIM * ODIM * IDIM;
    const float* ccf = g_cct + (size_t)f * (SPOS * CDIM);
    float a0 = 0.f, a1 = 0.f, a2 = 0.f, a3 = 0.f;

    for (int c0 = 0; c0 < CDIM; c0 += CBLK) {
        __syncthreads();
        {
            const float4* src = (const float4*)(Wf + c0 * ODIM * IDIM);
            float4* dst = (float4*)Wsm;
            dst[tid] = src[tid];
            dst[tid + 128] = src[tid + 128];
            #pragma unroll
            for (int k = tid; k < STILE * CBLK * IDIM / 4; k += 128) {
                int ss = k >> 4, q = k & 15;
                float4 pv = ((const float4*)(g_patch +
                    ((size_t)(st * STILE + ss) * CDIM + c0) * IDIM))[q];
                *(float4*)&Psm[ss][q * 4] = pv;
            }
            if (tid < 64) {
                int ss = tid >> 1, q = tid & 1;
                float4 cv = *(const float4*)(ccf +
                    (size_t)(st * STILE + ss) * CDIM + c0 + q * 4);
                *(float4*)&Csm[ss][q * 4] = cv;
            }
        }
        __syncthreads();
        #pragma unroll
        for (int cc = 0; cc < CBLK; cc++) {
            float ccv = Csm[s][cc];
            float4 pa = *(const float4*)&Psm[s][cc * 8];
            float4 pb = *(const float4*)&Psm[s][cc * 8 + 4];
            const float4* wr = (const float4*)&Wsm[(cc * 16 + warp * 4) * 8];
            a0 += ccv * dot8(wr[0], wr[1], pa, pb);
            a1 += ccv * dot8(wr[2], wr[3], pa, pb);
            a2 += ccv * dot8(wr[4], wr[5], pa, pb);
            a3 += ccv * dot8(wr[6], wr[7], pa, pb);
        }
    }

    Cent[s][warp * 4 + 0] = a0;
    Cent[s][warp * 4 + 1] = a1;
    Cent[s][warp * 4 + 2] = a2;
    Cent[s][warp * 4 + 3] = a3;
    __syncthreads();
    if (tid < STILE) {
        float sn = 0.f;
        #pragma unroll
        for (int o = 0; o < 16; o++) { float v = Cent[tid][o]; sn += v * v; }
        Fac[tid] = sn / ((1.f + sn) * sqrtf(sn + 1e-7f));
    }
    __syncthreads();
    float fc = Fac[s];
    float4 res = make_float4(a0 * fc, a1 * fc, a2 * fc, a3 * fc);
    *(float4*)(out + ((size_t)(st * STILE + s) * FDIM + f) * ODIM + warp * 4) = res;
}

// ---------------------------------------------------------------------------
extern "C" void kernel_launch(void* const* d_in, const int* in_sizes, int n_in,
                              void* d_out, int out_size) {
    const float* x  = (const float*)d_in[0];
    const float* Wg = (const float*)d_in[1];
    // Defensive: x has 200704 elems, W has 1179648 — swap if order differs.
    if (n_in >= 2 && in_sizes[0] == 1179648) { const float* t = x; x = Wg; Wg = t; }
    float* out = (float*)d_out;

    k_extract<<<(SPOS * CDIM * 2 + 255) / 256, 256>>>((const float4*)x);
    dim3 g(FDIM, SPOS / STILE);   // (32, 18)
    k_phase1<<<g, 128>>>(Wg);
    k_softmax<<<(SPOS * CDIM + 255) / 256, 256>>>();
    k_phase3<<<g, 128>>>(Wg, out);
}

// round 6
// speedup vs baseline: 2.2393x; 2.2393x over previous
#include <cuda_runtime.h>
#include <math.h>

#define SPOS 576      // B*Ho*Wo = 4*12*12
#define CDIM 288      // KH*KW*Fin
#define FDIM 32
#define ODIM 16
#define IDIM 8
#define CBLK 8
#define STILE 64      // s per CTA; 576/64 = 9 tiles

// Scratch (no allocations allowed)
__device__ float g_patchT[(size_t)CDIM * IDIM * SPOS];   // [c*8+i][s]   5.3 MB
__device__ float g_agreeT[(size_t)FDIM * CDIM * SPOS];   // [f][c][s]   21 MB
__device__ float g_cct  [(size_t)FDIM * CDIM * SPOS];    // [f][c][s]   21 MB

// ---------------------------------------------------------------------------
// K0: im2col + transpose — g_patchT[(c*8+i)*SPOS + s] = x[b,h+kh,w+kw,fin,i]
// One thread per (c,s): reads its 8 floats contiguously (one 32B sector),
// issues 8 coalesced stores (consecutive lanes = consecutive s).
// ---------------------------------------------------------------------------
__global__ void k_extract(const float* __restrict__ x) {
    int t = blockIdx.x * blockDim.x + threadIdx.x;
    if (t >= CDIM * SPOS) return;
    int s = t % SPOS, c = t / SPOS;
    int w = s % 12, h = (s / 12) % 12, b = s / 144;
    int fin = c & 31, kw = (c >> 5) % 3, kh = c / 96;
    const float* src = x + (size_t)((((b * 14 + h + kh) * 14 + (w + kw)) * 32 + fin)) * 8;
    float4 v0 = *(const float4*)src;
    float4 v1 = *(const float4*)(src + 4);
    float* dst = g_patchT + (size_t)c * 8 * SPOS + s;
    dst[0 * SPOS] = v0.x; dst[1 * SPOS] = v0.y; dst[2 * SPOS] = v0.z; dst[3 * SPOS] = v0.w;
    dst[4 * SPOS] = v1.x; dst[5 * SPOS] = v1.y; dst[6 * SPOS] = v1.z; dst[7 * SPOS] = v1.w;
}

// ---------------------------------------------------------------------------
// K1: per (f, 64-s tile): pass1 centroid1 -> squash -> out1; pass2 agreement.
// 128 threads = 4 warps. Pass1: warp -> 4 o's, lane -> s-pair (2 s).
// Pass2: warp -> 2 c's per c-block, lane -> s-pair; out1 cached in regs.
// ---------------------------------------------------------------------------
__global__ void __launch_bounds__(128) k_phase1(const float* __restrict__ Wg) {
    const int f = blockIdx.x, st = blockIdx.y;
    const int tid = threadIdx.x, warp = tid >> 5, lane = tid & 31;
    const int sbase = st * STILE;

    __shared__ float Wsm[CBLK * ODIM * IDIM];        // [cc][o][i]  4KB
    __shared__ float Ptile[CBLK * IDIM][STILE];      // [cc*8+i][s] 16KB
    __shared__ float Out1[ODIM][STILE];
    __shared__ float Cent[ODIM][STILE];
    __shared__ float Fac[STILE];

    const float* Wf = Wg + (size_t)f * CDIM * ODIM * IDIM;

    float2 acc[4];
    #pragma unroll
    for (int o = 0; o < 4; o++) acc[o] = make_float2(0.f, 0.f);

    // ---------------- pass 1: centroid ----------------
    for (int c0 = 0; c0 < CDIM; c0 += CBLK) {
        __syncthreads();
        {   // W chunk: CBLK*128 floats contiguous
            const float4* src = (const float4*)(Wf + c0 * ODIM * IDIM);
            ((float4*)Wsm)[tid]       = src[tid];
            ((float4*)Wsm)[tid + 128] = src[tid + 128];
            // P: 64 rows x 64 s = 1024 float4, 8 per thread
            #pragma unroll
            for (int k = 0; k < 8; k++) {
                int flat = tid + k * 128;
                int row = flat >> 4, q = flat & 15;
                float4 v = *(const float4*)(g_patchT + (size_t)(c0 * 8 + row) * SPOS + sbase + q * 4);
                *(float4*)&Ptile[row][q * 4] = v;
            }
        }
        __syncthreads();
        #pragma unroll
        for (int cc = 0; cc < CBLK; cc++) {
            float2 p[8];
            #pragma unroll
            for (int i = 0; i < 8; i++) p[i] = *(float2*)&Ptile[cc * 8 + i][2 * lane];
            #pragma unroll
            for (int o = 0; o < 4; o++) {
                const float4* wr = (const float4*)&Wsm[(cc * 16 + warp * 4 + o) * 8];
                float4 w0 = wr[0], w1 = wr[1];
                acc[o].x += w0.x*p[0].x + w0.y*p[1].x + w0.z*p[2].x + w0.w*p[3].x
                          + w1.x*p[4].x + w1.y*p[5].x + w1.z*p[6].x + w1.w*p[7].x;
                acc[o].y += w0.x*p[0].y + w0.y*p[1].y + w0.z*p[2].y + w0.w*p[3].y
                          + w1.x*p[4].y + w1.y*p[5].y + w1.z*p[6].y + w1.w*p[7].y;
            }
        }
    }

    const float inv32 = 1.f / 32.f;
    #pragma unroll
    for (int o = 0; o < 4; o++)
        *(float2*)&Cent[warp * 4 + o][2 * lane] =
            make_float2(acc[o].x * inv32, acc[o].y * inv32);
    __syncthreads();
    if (tid < STILE) {
        float sn = 0.f;
        #pragma unroll
        for (int o = 0; o < 16; o++) { float v = Cent[o][tid]; sn += v * v; }
        Fac[tid] = sn / ((1.f + sn) * sqrtf(sn + 1e-7f));
    }
    __syncthreads();
    {
        float fx = Fac[2 * lane] * inv32, fy = Fac[2 * lane + 1] * inv32;
        #pragma unroll
        for (int o = 0; o < 4; o++)
            *(float2*)&Out1[warp * 4 + o][2 * lane] =
                make_float2(acc[o].x * fx, acc[o].y * fy);
    }
    __syncthreads();

    // hoist out1 for this thread's s-pair into registers (all 16 o)
    float2 o1[16];
    #pragma unroll
    for (int o = 0; o < 16; o++) o1[o] = *(float2*)&Out1[o][2 * lane];

    // ---------------- pass 2: agreement ----------------
    for (int c0 = 0; c0 < CDIM; c0 += CBLK) {
        __syncthreads();
        {
            const float4* src = (const float4*)(Wf + c0 * ODIM * IDIM);
            ((float4*)Wsm)[tid]       = src[tid];
            ((float4*)Wsm)[tid + 128] = src[tid + 128];
            #pragma unroll
            for (int k = 0; k < 8; k++) {
                int flat = tid + k * 128;
                int row = flat >> 4, q = flat & 15;
                float4 v = *(const float4*)(g_patchT + (size_t)(c0 * 8 + row) * SPOS + sbase + q * 4);
                *(float4*)&Ptile[row][q * 4] = v;
            }
        }
        __syncthreads();
        #pragma unroll
        for (int j = 0; j < 2; j++) {
            int cc = warp * 2 + j;
            float2 p[8];
            #pragma unroll
            for (int i = 0; i < 8; i++) p[i] = *(float2*)&Ptile[cc * 8 + i][2 * lane];
            float ax = 0.f, ay = 0.f;
            #pragma unroll
            for (int o = 0; o < 16; o++) {
                const float4* wr = (const float4*)&Wsm[(cc * 16 + o) * 8];
                float4 w0 = wr[0], w1 = wr[1];
                float px = w0.x*p[0].x + w0.y*p[1].x + w0.z*p[2].x + w0.w*p[3].x
                         + w1.x*p[4].x + w1.y*p[5].x + w1.z*p[6].x + w1.w*p[7].x;
                float py = w0.x*p[0].y + w0.y*p[1].y + w0.z*p[2].y + w0.w*p[3].y
                         + w1.x*p[4].y + w1.y*p[5].y + w1.z*p[6].y + w1.w*p[7].y;
                ax += px * o1[o].x;
                ay += py * o1[o].y;
            }
            *(float2*)&g_agreeT[((size_t)f * CDIM + c0 + cc) * SPOS + sbase + 2 * lane] =
                make_float2(ax, ay);
        }
    }
}

// ---------------------------------------------------------------------------
// K2: softmax over f for each (c,s) column. [f][c][s] layout -> fully
// coalesced strided loads/stores, one thread per column.
// ---------------------------------------------------------------------------
__global__ void k_softmax() {
    int j = blockIdx.x * blockDim.x + threadIdx.x;
    if (j >= CDIM * SPOS) return;
    float v[32];
    float mx = -1e30f;
    #pragma unroll
    for (int ff = 0; ff < 32; ff++) {
        v[ff] = g_agreeT[(size_t)ff * (CDIM * SPOS) + j];
        mx = fmaxf(mx, v[ff]);
    }
    float sum = 0.f;
    #pragma unroll
    for (int ff = 0; ff < 32; ff++) { v[ff] = __expf(v[ff] - mx); sum += v[ff]; }
    float inv = 1.f / sum;
    #pragma unroll
    for (int ff = 0; ff < 32; ff++)
        g_cct[(size_t)ff * (CDIM * SPOS) + j] = v[ff] * inv;
}

// ---------------------------------------------------------------------------
// K3: centroid2 = sum_c cc * preds ; squash ; write output [s][f][o]
// Same blocking as k_phase1 pass1 + cc weights from smem.
// ---------------------------------------------------------------------------
__global__ void __launch_bounds__(128) k_phase3(const float* __restrict__ Wg,
                                                float* __restrict__ out) {
    const int f = blockIdx.x, st = blockIdx.y;
    const int tid = threadIdx.x, warp = tid >> 5, lane = tid & 31;
    const int sbase = st * STILE;

    __shared__ float Wsm[CBLK * ODIM * IDIM];
    __shared__ float Ptile[CBLK * IDIM][STILE];
    __shared__ float Csm[CBLK][STILE];
    __shared__ float Cent[ODIM][STILE];
    __shared__ float Fac[STILE];

    const float* Wf  = Wg + (size_t)f * CDIM * ODIM * IDIM;
    const float* ccf = g_cct + (size_t)f * (CDIM * SPOS);

    float2 acc[4];
    #pragma unroll
    for (int o = 0; o < 4; o++) acc[o] = make_float2(0.f, 0.f);

    for (int c0 = 0; c0 < CDIM; c0 += CBLK) {
        __syncthreads();
        {
            const float4* src = (const float4*)(Wf + c0 * ODIM * IDIM);
            ((float4*)Wsm)[tid]       = src[tid];
            ((float4*)Wsm)[tid + 128] = src[tid + 128];
            #pragma unroll
            for (int k = 0; k < 8; k++) {
                int flat = tid + k * 128;
                int row = flat >> 4, q = flat & 15;
                float4 v = *(const float4*)(g_patchT + (size_t)(c0 * 8 + row) * SPOS + sbase + q * 4);
                *(float4*)&Ptile[row][q * 4] = v;
            }
            {   // cc tile: 8 rows x 64 s = 128 float4, 1 per thread
                int row = tid >> 4, q = tid & 15;
                float4 cv = *(const float4*)(ccf + (size_t)(c0 + row) * SPOS + sbase + q * 4);
                *(float4*)&Csm[row][q * 4] = cv;
            }
        }
        __syncthreads();
        #pragma unroll
        for (int cc = 0; cc < CBLK; cc++) {
            float2 cv = *(float2*)&Csm[cc][2 * lane];
            float2 p[8];
            #pragma unroll
            for (int i = 0; i < 8; i++) p[i] = *(float2*)&Ptile[cc * 8 + i][2 * lane];
            #pragma unroll
            for (int o = 0; o < 4; o++) {
                const float4* wr = (const float4*)&Wsm[(cc * 16 + warp * 4 + o) * 8];
                float4 w0 = wr[0], w1 = wr[1];
                float px = w0.x*p[0].x + w0.y*p[1].x + w0.z*p[2].x + w0.w*p[3].x
                         + w1.x*p[4].x + w1.y*p[5].x + w1.z*p[6].x + w1.w*p[7].x;
                float py = w0.x*p[0].y + w0.y*p[1].y + w0.z*p[2].y + w0.w*p[3].y
                         + w1.x*p[4].y + w1.y*p[5].y + w1.z*p[6].y + w1.w*p[7].y;
                acc[o].x += cv.x * px;
                acc[o].y += cv.y * py;
            }
        }
    }

    #pragma unroll
    for (int o = 0; o < 4; o++)
        *(float2*)&Cent[warp * 4 + o][2 * lane] = acc[o];
    __syncthreads();
    if (tid < STILE) {
        float sn = 0.f;
        #pragma unroll
        for (int o = 0; o < 16; o++) { float v = Cent[o][tid]; sn += v * v; }
        Fac[tid] = sn / ((1.f + sn) * sqrtf(sn + 1e-7f));
    }
    __syncthreads();
    {
        float fx = Fac[2 * lane], fy = Fac[2 * lane + 1];
        int s0 = sbase + 2 * lane;
        float4 r0 = make_float4(acc[0].x * fx, acc[1].x * fx, acc[2].x * fx, acc[3].x * fx);
        float4 r1 = make_float4(acc[0].y * fy, acc[1].y * fy, acc[2].y * fy, acc[3].y * fy);
        *(float4*)(out + ((size_t)s0       * FDIM + f) * ODIM + warp * 4) = r0;
        *(float4*)(out + ((size_t)(s0 + 1) * FDIM + f) * ODIM + warp * 4) = r1;
    }
}

// ---------------------------------------------------------------------------
extern "C" void kernel_launch(void* const* d_in, const int* in_sizes, int n_in,
                              void* d_out, int out_size) {
    const float* x  = (const float*)d_in[0];
    const float* Wg = (const float*)d_in[1];
    if (n_in >= 2 && in_sizes[0] == 1179648) { const float* t = x; x = Wg; Wg = t; }
    float* out = (float*)d_out;

    k_extract<<<(CDIM * SPOS + 255) / 256, 256>>>(x);
    dim3 g(FDIM, SPOS / STILE);   // (32, 9) = 288 CTAs, single balanced wave
    k_phase1<<<g, 128>>>(Wg);
    k_softmax<<<(CDIM * SPOS + 255) / 256, 256>>>();
    k_phase3<<<g, 128>>>(Wg, out);
}

// round 9
// speedup vs baseline: 2.4828x; 1.1088x over previous
#include <cuda_runtime.h>
#include <math.h>

#define SPOS 576      // B*Ho*Wo = 4*12*12
#define CDIM 288      // KH*KW*Fin
#define FDIM 32
#define ODIM 16
#define CBLK 8
#define STILE 64
#define NBLK (CDIM/CBLK)   // 36

typedef unsigned long long u64;

// Scratch (no allocations allowed)
__device__ float g_patch [(size_t)SPOS * CDIM * 8];      // [s][c][i]   5.3 MB
__device__ float g_agreeT[(size_t)FDIM * CDIM * SPOS];   // [f][c][s]  21 MB
__device__ float g_cct  [(size_t)FDIM * CDIM * SPOS];    // [f][c][s]  21 MB

// dynamic smem layout (floats)
#define OFF_W    0                       // 4 groups x 1024
#define OFF_P    4096                    // 4 groups x (64*68)
#define PSTR     68
#define PGRP     (STILE * PSTR)          // 4352
#define OFF_CENT 21504                   // 16 x 64
#define OFF_FAC  22528                   // 64
#define OFF_CSM  22592                   // 4 groups x 512
#define SMEM_FLOATS 24640
#define SMEM_BYTES  (SMEM_FLOATS * 4)

__device__ __forceinline__ void fma2(u64& d, u64 a, u64 b) {
    asm("fma.rn.f32x2 %0, %1, %2, %0;" : "+l"(d) : "l"(a), "l"(b));
}
__device__ __forceinline__ float2 u2f(u64 v) {
    float2 f; asm("mov.b64 {%0,%1}, %2;" : "=f"(f.x), "=f"(f.y) : "l"(v)); return f;
}
__device__ __forceinline__ u64 f2u(float x, float y) {
    u64 v; asm("mov.b64 %0, {%1,%2};" : "=l"(v) : "f"(x), "f"(y)); return v;
}

// ---------------------------------------------------------------------------
// K0: im2col — g_patch[s][c][i] = x[b,h+kh,w+kw,fin,i]
// ---------------------------------------------------------------------------
__global__ void k_extract(const float4* __restrict__ x4) {
    int idx = blockIdx.x * blockDim.x + threadIdx.x;   // SPOS*CDIM*2 float4s
    if (idx >= SPOS * CDIM * 2) return;
    int v = idx & 1;
    int c = (idx >> 1) % CDIM;
    int s = idx / (CDIM * 2);
    int w = s % 12, h = (s / 12) % 12, b = s / 144;
    int fin = c & 31, kw = (c >> 5) % 3, kh = c / 96;
    int xi = (((b * 14 + h + kh) * 14 + (w + kw)) * 32 + fin) * 2 + v;
    ((float4*)g_patch)[idx] = x4[xi];
}

// group loader: 64 threads bring W chunk (4KB) + P tile (64s x 64 floats)
__device__ __forceinline__ void load_tiles(float* Wsm, float* Pt,
                                           const float* Wf, int c0,
                                           int sbase, int wtid) {
    const float4* wsrc = (const float4*)(Wf + c0 * 128);
    float4* wdst = (float4*)Wsm;
    #pragma unroll
    for (int k = 0; k < 4; k++) wdst[wtid + k * 64] = wsrc[wtid + k * 64];
    #pragma unroll
    for (int k = 0; k < 16; k++) {
        int flat = wtid + k * 64;
        int s = flat >> 4, q = flat & 15;
        float4 v = *(const float4*)(g_patch + (size_t)(sbase + s) * (CDIM * 8)
                                    + c0 * 8 + q * 4);
        *(float4*)(Pt + s * PSTR + q * 4) = v;
    }
}

// ---------------------------------------------------------------------------
// K1: per (f, 64-s tile), 256 thr = 4 c-groups x 2 o-halves.
// Pass1 centroid (packed-i FMA2) -> squash -> out1 regs; pass2 agreement.
// ---------------------------------------------------------------------------
__global__ void __launch_bounds__(256) k_phase1(const float* __restrict__ Wg) {
    extern __shared__ float sm[];
    const int f = blockIdx.x, st = blockIdx.y;
    const int tid = threadIdx.x, warp = tid >> 5, lane = tid & 31;
    const int g = warp >> 1, h = warp & 1, wtid = tid & 63;
    const int sbase = st * STILE;
    float* Wsm  = sm + OFF_W + g * 1024;
    float* Pt   = sm + OFF_P + g * PGRP;
    float* Cent = sm + OFF_CENT;
    float* Fac  = sm + OFF_FAC;
    const float* Wf = Wg + (size_t)f * CDIM * 128;

    for (int k = tid; k < ODIM * STILE; k += 256) Cent[k] = 0.f;
    __syncthreads();

    const u64* Pr0 = (const u64*)(Pt + (2 * lane) * PSTR);
    const u64* Pr1 = (const u64*)(Pt + (2 * lane + 1) * PSTR);

    u64 acc[8][2];
    #pragma unroll
    for (int o = 0; o < 8; o++) { acc[o][0] = 0ULL; acc[o][1] = 0ULL; }

    // ---------------- pass 1 ----------------
    for (int blk = g; blk < NBLK; blk += 4) {
        int c0 = blk * CBLK;
        asm volatile("bar.sync %0, 64;" :: "r"(g + 1) : "memory");
        load_tiles(Wsm, Pt, Wf, c0, sbase, wtid);
        asm volatile("bar.sync %0, 64;" :: "r"(g + 1) : "memory");
        #pragma unroll
        for (int cc = 0; cc < CBLK; cc++) {
            ulonglong2 qa0 = *(const ulonglong2*)(Pr0 + cc * 4);
            ulonglong2 qa1 = *(const ulonglong2*)(Pr0 + cc * 4 + 2);
            ulonglong2 qb0 = *(const ulonglong2*)(Pr1 + cc * 4);
            ulonglong2 qb1 = *(const ulonglong2*)(Pr1 + cc * 4 + 2);
            #pragma unroll
            for (int o = 0; o < 8; o++) {
                const ulonglong2* wr = (const ulonglong2*)(Wsm + (cc * 16 + h * 8 + o) * 8);
                ulonglong2 w0 = wr[0], w1 = wr[1];
                fma2(acc[o][0], w0.x, qa0.x); fma2(acc[o][0], w0.y, qa0.y);
                fma2(acc[o][0], w1.x, qa1.x); fma2(acc[o][0], w1.y, qa1.y);
                fma2(acc[o][1], w0.x, qb0.x); fma2(acc[o][1], w0.y, qb0.y);
                fma2(acc[o][1], w1.x, qb1.x); fma2(acc[o][1], w1.y, qb1.y);
            }
        }
    }
    #pragma unroll
    for (int o = 0; o < 8; o++) {
        float2 v0 = u2f(acc[o][0]), v1 = u2f(acc[o][1]);
        atomicAdd(&Cent[(h * 8 + o) * STILE + 2 * lane],     v0.x + v0.y);
        atomicAdd(&Cent[(h * 8 + o) * STILE + 2 * lane + 1], v1.x + v1.y);
    }
    __syncthreads();
    if (tid < STILE) {
        const float inv32 = 1.f / 32.f;
        float sn = 0.f;
        #pragma unroll
        for (int o = 0; o < 16; o++) { float v = Cent[o * STILE + tid] * inv32; sn += v * v; }
        Fac[tid] = (sn / ((1.f + sn) * sqrtf(sn + 1e-7f))) * inv32;  // fold /32
    }
    __syncthreads();
    float fw0 = Fac[2 * lane], fw1 = Fac[2 * lane + 1];
    float2 o1[16];
    #pragma unroll
    for (int o = 0; o < 16; o++) {
        float2 cv = *(float2*)&Cent[o * STILE + 2 * lane];
        o1[o] = make_float2(cv.x * fw0, cv.y * fw1);
    }

    // ---------------- pass 2: agreement ----------------
    for (int blk = g; blk < NBLK; blk += 4) {
        int c0 = blk * CBLK;
        asm volatile("bar.sync %0, 64;" :: "r"(g + 1) : "memory");
        load_tiles(Wsm, Pt, Wf, c0, sbase, wtid);
        asm volatile("bar.sync %0, 64;" :: "r"(g + 1) : "memory");
        #pragma unroll
        for (int j = 0; j < 4; j++) {
            int cc = h * 4 + j;
            ulonglong2 qa0 = *(const ulonglong2*)(Pr0 + cc * 4);
            ulonglong2 qa1 = *(const ulonglong2*)(Pr0 + cc * 4 + 2);
            ulonglong2 qb0 = *(const ulonglong2*)(Pr1 + cc * 4);
            ulonglong2 qb1 = *(const ulonglong2*)(Pr1 + cc * 4 + 2);
            u64 ag0 = 0ULL, ag1 = 0ULL;
            #pragma unroll
            for (int o = 0; o < 16; o++) {
                const ulonglong2* wr = (const ulonglong2*)(Wsm + (cc * 16 + o) * 8);
                ulonglong2 w0 = wr[0], w1 = wr[1];
                u64 pr0 = 0ULL, pr1 = 0ULL;
                fma2(pr0, w0.x, qa0.x); fma2(pr0, w0.y, qa0.y);
                fma2(pr0, w1.x, qa1.x); fma2(pr0, w1.y, qa1.y);
                fma2(pr1, w0.x, qb0.x); fma2(pr1, w0.y, qb0.y);
                fma2(pr1, w1.x, qb1.x); fma2(pr1, w1.y, qb1.y);
                fma2(ag0, f2u(o1[o].x, o1[o].x), pr0);
                fma2(ag1, f2u(o1[o].y, o1[o].y), pr1);
            }
            float2 r0 = u2f(ag0), r1 = u2f(ag1);
            *(float2*)&g_agreeT[((size_t)f * CDIM + c0 + cc) * SPOS + sbase + 2 * lane] =
                make_float2(r0.x + r0.y, r1.x + r1.y);
        }
    }
}

// ---------------------------------------------------------------------------
// K2: softmax over f per (c,s) column; [f][c][s] layout, fully coalesced.
// ---------------------------------------------------------------------------
__global__ void k_softmax() {
    int j = blockIdx.x * blockDim.x + threadIdx.x;
    if (j >= CDIM * SPOS) return;
    float v[32];
    float mx = -1e30f;
    #pragma unroll
    for (int ff = 0; ff < 32; ff++) {
        v[ff] = g_agreeT[(size_t)ff * (CDIM * SPOS) + j];
        mx = fmaxf(mx, v[ff]);
    }
    float sum = 0.f;
    #pragma unroll
    for (int ff = 0; ff < 32; ff++) { v[ff] = __expf(v[ff] - mx); sum += v[ff]; }
    float inv = 1.f / sum;
    #pragma unroll
    for (int ff = 0; ff < 32; ff++)
        g_cct[(size_t)ff * (CDIM * SPOS) + j] = v[ff] * inv;
}

// ---------------------------------------------------------------------------
// K3: centroid2 = sum_c cc * preds ; squash ; out[s][f][o]
// ---------------------------------------------------------------------------
__global__ void __launch_bounds__(256) k_phase3(const float* __restrict__ Wg,
                                                float* __restrict__ out) {
    extern __shared__ float sm[];
    const int f = blockIdx.x, st = blockIdx.y;
    const int tid = threadIdx.x, warp = tid >> 5, lane = tid & 31;
    const int g = warp >> 1, h = warp & 1, wtid = tid & 63;
    const int sbase = st * STILE;
    float* Wsm  = sm + OFF_W + g * 1024;
    float* Pt   = sm + OFF_P + g * PGRP;
    float* Cent = sm + OFF_CENT;
    float* Fac  = sm + OFF_FAC;
    float* Csm  = sm + OFF_CSM + g * (CBLK * STILE);
    const float* Wf  = Wg + (size_t)f * CDIM * 128;
    const float* ccf = g_cct + (size_t)f * (CDIM * SPOS);

    for (int k = tid; k < ODIM * STILE; k += 256) Cent[k] = 0.f;
    __syncthreads();

    const u64* Pr0 = (const u64*)(Pt + (2 * lane) * PSTR);
    const u64* Pr1 = (const u64*)(Pt + (2 * lane + 1) * PSTR);

    u64 acc[8][2];
    #pragma unroll
    for (int o = 0; o < 8; o++) { acc[o][0] = 0ULL; acc[o][1] = 0ULL; }

    for (int blk = g; blk < NBLK; blk += 4) {
        int c0 = blk * CBLK;
        asm volatile("bar.sync %0, 64;" :: "r"(g + 1) : "memory");
        load_tiles(Wsm, Pt, Wf, c0, sbase, wtid);
        #pragma unroll
        for (int k = 0; k < 2; k++) {   // cc tile: 8 x 64 floats
            int flat = wtid + k * 64;
            int cc = flat >> 4, q = flat & 15;
            float4 v = *(const float4*)(ccf + (size_t)(c0 + cc) * SPOS + sbase + q * 4);
            *(float4*)(Csm + cc * STILE + q * 4) = v;
        }
        asm volatile("bar.sync %0, 64;" :: "r"(g + 1) : "memory");
        #pragma unroll
        for (int cc = 0; cc < CBLK; cc++) {
            float2 cv = *(float2*)&Csm[cc * STILE + 2 * lane];
            u64 cda = f2u(cv.x, cv.x), cdb = f2u(cv.y, cv.y);
            ulonglong2 qa0 = *(const ulonglong2*)(Pr0 + cc * 4);
            ulonglong2 qa1 = *(const ulonglong2*)(Pr0 + cc * 4 + 2);
            ulonglong2 qb0 = *(const ulonglong2*)(Pr1 + cc * 4);
            ulonglong2 qb1 = *(const ulonglong2*)(Pr1 + cc * 4 + 2);
            #pragma unroll
            for (int o = 0; o < 8; o++) {
                const ulonglong2* wr = (const ulonglong2*)(Wsm + (cc * 16 + h * 8 + o) * 8);
                ulonglong2 w0 = wr[0], w1 = wr[1];
                u64 pr0 = 0ULL, pr1 = 0ULL;
                fma2(pr0, w0.x, qa0.x); fma2(pr0, w0.y, qa0.y);
                fma2(pr0, w1.x, qa1.x); fma2(pr0, w1.y, qa1.y);
                fma2(pr1, w0.x, qb0.x); fma2(pr1, w0.y, qb0.y);
                fma2(pr1, w1.x, qb1.x); fma2(pr1, w1.y, qb1.y);
                fma2(acc[o][0], cda, pr0);
                fma2(acc[o][1], cdb, pr1);
            }
        }
    }
    #pragma unroll
    for (int o = 0; o < 8; o++) {
        float2 v0 = u2f(acc[o][0]), v1 = u2f(acc[o][1]);
        atomicAdd(&Cent[(h * 8 + o) * STILE + 2 * lane],     v0.x + v0.y);
        atomicAdd(&Cent[(h * 8 + o) * STILE + 2 * lane + 1], v1.x + v1.y);
    }
    __syncthreads();
    if (tid < STILE) {
        float sn = 0.f;
        #pragma unroll
        for (int o = 0; o < 16; o++) { float v = Cent[o * STILE + tid]; sn += v * v; }
        Fac[tid] = sn / ((1.f + sn) * sqrtf(sn + 1e-7f));
    }
    __syncthreads();
    {
        int s = tid >> 2, oq = tid & 3;    // 64 s x 4 o-quads = 256
        float fs = Fac[s];
        float4 r;
        r.x = Cent[(oq * 4 + 0) * STILE + s] * fs;
        r.y = Cent[(oq * 4 + 1) * STILE + s] * fs;
        r.z = Cent[(oq * 4 + 2) * STILE + s] * fs;
        r.w = Cent[(oq * 4 + 3) * STILE + s] * fs;
        *(float4*)(out + ((size_t)(sbase + s) * FDIM + f) * ODIM + oq * 4) = r;
    }
}

// ---------------------------------------------------------------------------
extern "C" void kernel_launch(void* const* d_in, const int* in_sizes, int n_in,
                              void* d_out, int out_size) {
    const float* x  = (const float*)d_in[0];
    const float* Wg = (const float*)d_in[1];
    if (n_in >= 2 && in_sizes[0] == 1179648) { const float* t = x; x = Wg; Wg = t; }
    float* out = (float*)d_out;

    cudaFuncSetAttribute(k_phase1, cudaFuncAttributeMaxDynamicSharedMemorySize, SMEM_BYTES);
    cudaFuncSetAttribute(k_phase3, cudaFuncAttributeMaxDynamicSharedMemorySize, SMEM_BYTES);

    k_extract<<<(SPOS * CDIM * 2 + 255) / 256, 256>>>((const float4*)x);
    dim3 g(FDIM, SPOS / STILE);   // (32, 9) = 288 CTAs, 2 CTAs/SM wave
    k_phase1<<<g, 256, SMEM_BYTES>>>(Wg);
    k_softmax<<<(CDIM * SPOS + 255) / 256, 256>>>();
    k_phase3<<<g, 256, SMEM_BYTES>>>(Wg, out);
}